// round 8
// baseline (speedup 1.0000x reference)
#include <cuda_runtime.h>
#include <cuda_bf16.h>
#include <cstdint>

#define NDIM 384
#define MAT  (NDIM*NDIM)
#define NMAT 256
#define CH   128
#define EPS  1e-5f

typedef __nv_bfloat16 bf16;

// ---- scratch (static device globals; no allocation) ----
__device__ bf16  g_Xa[(size_t)NMAT*MAT];
__device__ bf16  g_Xb[(size_t)NMAT*MAT];
__device__ bf16  g_S [(size_t)NMAT*MAT];
__device__ bf16  g_Bq[(size_t)NMAT*MAT];
__device__ bf16  g_Ab[(size_t)NMAT*MAT];
__device__ float g_cA[NMAT];        // qc * gamma^5
__device__ float g_cB[NMAT];        // qb * gamma^3
__device__ float g_cX[NMAT];        // qa * gamma
__device__ float g_part[NMAT * 9];  // per-tile <G,S> partials
__device__ float g_p [NMAT];

__device__ __forceinline__ uint32_t smem_to_u32(const void* p) {
    uint32_t a;
    asm("{ .reg .u64 t; cvta.to.shared.u64 t, %1; cvt.u32.u64 %0, t; }" : "=r"(a) : "l"(p));
    return a;
}

__device__ __forceinline__ float block_reduce(float s) {
    __shared__ float sh[32];
    for (int o = 16; o; o >>= 1) s += __shfl_down_sync(0xFFFFFFFFu, s, o);
    if ((threadIdx.x & 31) == 0) sh[threadIdx.x >> 5] = s;
    __syncthreads();
    float r = 0.f;
    if (threadIdx.x < 32) {
        r = (threadIdx.x < (blockDim.x >> 5)) ? sh[threadIdx.x] : 0.f;
        for (int o = 16; o; o >>= 1) r += __shfl_down_sync(0xFFFFFFFFu, r, o);
    }
    __syncthreads();
    return r;
}

// ================= batched bf16 GEMM via mma.sync =================
// TRANS_B=0 (NT): C = a*A*B^T + b*Add   TRANS_B=1 (NN): C = a*A*B + b*Add
// SYMM=1: output symmetric, 6 upper tiles + mirrored writes.
// DOT=1: no C written; accumulate <a*A*B^T, Add> per-CTA into g_part.
// Per-matrix coefficients via aArr/bArr (override alpha/beta when non-null).
// __launch_bounds__(256, 2): pin regs <=128 so 2 CTAs co-reside per SM
// (2*32K regs = full RF, 2*96KB smem = 192KB <= 228KB).
#define GSMEM (3 * 32768)

template<int TRANS_B, int SYMM, int DOT>
__global__ void __launch_bounds__(256, 2) gemm_mma(
    const bf16* __restrict__ gA, const bf16* __restrict__ gB,
    const bf16* __restrict__ gAdd, bf16* __restrict__ gC,
    float alpha, float beta,
    const float* __restrict__ aArr, const float* __restrict__ bArr)
{
    extern __shared__ char smem_raw[];
    const int m = blockIdx.z;
    int bi, bj;
    if (SYMM) {
        int x = blockIdx.x;
        bi = (x < 3) ? 0 : (x < 5) ? 1 : 2;
        bj = (x < 3) ? x : (x < 5) ? (x - 2) : 2;
    } else {
        bi = blockIdx.y; bj = blockIdx.x;
    }
    const int row0 = bi * 128, col0 = bj * 128;
    const bf16* A = gA + (size_t)m * MAT + (size_t)row0 * NDIM;
    const bf16* B = TRANS_B ? (gB + (size_t)m * MAT + col0)
                            : (gB + (size_t)m * MAT + (size_t)col0 * NDIM);
    const uint32_t sBase = smem_to_u32(smem_raw);
    const int tid = threadIdx.x;
    const int wid = tid >> 5, lane = tid & 31;
    const int wm = wid >> 2, wn = wid & 3;

    auto issue = [&](int kt, int stage) {
        uint32_t aD = sBase + stage * 32768;
        uint32_t bD = aD + 16384;
        const bf16* aSrc = A + kt * 64;
#pragma unroll
        for (int i = 0; i < 4; i++) {
            int c = tid + i * 256;
            int row = c >> 3, u = c & 7;
            uint32_t sw = (uint32_t)(row * 128 + ((u ^ (row & 7)) << 4));
            asm volatile("cp.async.cg.shared.global [%0], [%1], 16;"
                :: "r"(aD + sw), "l"(aSrc + (size_t)row * NDIM + u * 8) : "memory");
        }
        if (TRANS_B) {
            const bf16* bSrc = B + (size_t)(kt * 64) * NDIM;
#pragma unroll
            for (int i = 0; i < 4; i++) {
                int c = tid + i * 256;
                int row = c >> 4, u = c & 15;
                uint32_t sw = (uint32_t)(row * 256 + ((u ^ (row & 7)) << 4));
                asm volatile("cp.async.cg.shared.global [%0], [%1], 16;"
                    :: "r"(bD + sw), "l"(bSrc + (size_t)row * NDIM + u * 8) : "memory");
            }
        } else {
            const bf16* bSrc = B + kt * 64;
#pragma unroll
            for (int i = 0; i < 4; i++) {
                int c = tid + i * 256;
                int row = c >> 3, u = c & 7;
                uint32_t sw = (uint32_t)(row * 128 + ((u ^ (row & 7)) << 4));
                asm volatile("cp.async.cg.shared.global [%0], [%1], 16;"
                    :: "r"(bD + sw), "l"(bSrc + (size_t)row * NDIM + u * 8) : "memory");
            }
        }
        asm volatile("cp.async.commit_group;" ::: "memory");
    };

    float acc[4][4][4];
#pragma unroll
    for (int a = 0; a < 4; a++)
#pragma unroll
        for (int b = 0; b < 4; b++)
#pragma unroll
            for (int c = 0; c < 4; c++) acc[a][b][c] = 0.f;

    issue(0, 0);
    issue(1, 1);

    for (int kt = 0; kt < 6; kt++) {
        int stage = kt % 3;
        if (kt < 5) asm volatile("cp.async.wait_group 1;" ::: "memory");
        else        asm volatile("cp.async.wait_group 0;" ::: "memory");
        __syncthreads();
        if (kt + 2 < 6) issue(kt + 2, (kt + 2) % 3);
        uint32_t aS = sBase + stage * 32768;
        uint32_t bS = aS + 16384;
#pragma unroll
        for (int ks = 0; ks < 4; ks++) {
            uint32_t af[4][4];
            uint32_t bfr[4][2];
#pragma unroll
            for (int mi = 0; mi < 4; mi++) {
                int row = wm * 64 + mi * 16 + (lane & 15);
                int u = ks * 2 + (lane >> 4);
                uint32_t addr = aS + row * 128 + ((u ^ (row & 7)) << 4);
                asm volatile("ldmatrix.sync.aligned.m8n8.x4.shared.b16 {%0,%1,%2,%3}, [%4];"
                    : "=r"(af[mi][0]), "=r"(af[mi][1]), "=r"(af[mi][2]), "=r"(af[mi][3])
                    : "r"(addr));
            }
            if (TRANS_B) {
#pragma unroll
                for (int bj2 = 0; bj2 < 2; bj2++) {
                    int krow = ks * 16 + (lane & 15);
                    int ugrp = ((wn * 32 + bj2 * 16) >> 3) + (lane >> 4);
                    uint32_t addr = bS + krow * 256 + ((ugrp ^ (krow & 7)) << 4);
                    asm volatile("ldmatrix.sync.aligned.m8n8.x4.trans.shared.b16 {%0,%1,%2,%3}, [%4];"
                        : "=r"(bfr[bj2*2][0]), "=r"(bfr[bj2*2][1]),
                          "=r"(bfr[bj2*2+1][0]), "=r"(bfr[bj2*2+1][1])
                        : "r"(addr));
                }
            } else {
#pragma unroll
                for (int bj2 = 0; bj2 < 2; bj2++) {
                    int nLocal = wn * 32 + bj2 * 16 + ((lane >> 4) << 3) + (lane & 7);
                    int u = ks * 2 + ((lane >> 3) & 1);
                    uint32_t addr = bS + nLocal * 128 + ((u ^ (nLocal & 7)) << 4);
                    asm volatile("ldmatrix.sync.aligned.m8n8.x4.shared.b16 {%0,%1,%2,%3}, [%4];"
                        : "=r"(bfr[bj2*2][0]), "=r"(bfr[bj2*2][1]),
                          "=r"(bfr[bj2*2+1][0]), "=r"(bfr[bj2*2+1][1])
                        : "r"(addr));
                }
            }
#pragma unroll
            for (int mi = 0; mi < 4; mi++)
#pragma unroll
                for (int nj = 0; nj < 4; nj++) {
                    asm volatile(
                        "mma.sync.aligned.m16n8k16.row.col.f32.bf16.bf16.f32 "
                        "{%0,%1,%2,%3}, {%4,%5,%6,%7}, {%8,%9}, {%0,%1,%2,%3};"
                        : "+f"(acc[mi][nj][0]), "+f"(acc[mi][nj][1]),
                          "+f"(acc[mi][nj][2]), "+f"(acc[mi][nj][3])
                        : "r"(af[mi][0]), "r"(af[mi][1]), "r"(af[mi][2]), "r"(af[mi][3]),
                          "r"(bfr[nj][0]), "r"(bfr[nj][1]));
                }
        }
    }

    // ---- epilogue ----
    float a_ = aArr ? aArr[m] : alpha;
    float b_ = bArr ? bArr[m] : beta;
    bool useAdd = (bArr != nullptr) || (beta != 0.f);

    const int rL = wm * 64 + (lane >> 2);
    const int cL = wn * 32 + (lane & 3) * 2;
    const bf16* Add = gAdd + (size_t)m * MAT;

    if (DOT) {
        float part = 0.f;
#pragma unroll
        for (int mi = 0; mi < 4; mi++)
#pragma unroll
            for (int nj = 0; nj < 4; nj++) {
                int r = row0 + rL + mi * 16;
                int cc = col0 + cL + nj * 8;
                uint32_t w0 = *(const uint32_t*)(Add + (size_t)r * NDIM + cc);
                uint32_t w1 = *(const uint32_t*)(Add + (size_t)(r + 8) * NDIM + cc);
                __nv_bfloat162 b0 = *reinterpret_cast<__nv_bfloat162*>(&w0);
                __nv_bfloat162 b1 = *reinterpret_cast<__nv_bfloat162*>(&w1);
                part += acc[mi][nj][0] * __bfloat162float(b0.x);
                part += acc[mi][nj][1] * __bfloat162float(b0.y);
                part += acc[mi][nj][2] * __bfloat162float(b1.x);
                part += acc[mi][nj][3] * __bfloat162float(b1.y);
            }
        part = block_reduce(part);
        if (tid == 0) g_part[m * 9 + bi * 3 + bj] = part;
        return;
    }

    const bool mirror = SYMM && (row0 != col0);
    if (mirror) __syncthreads();
    uint16_t* stageB = (uint16_t*)smem_raw;   // stride 130

#pragma unroll
    for (int mi = 0; mi < 4; mi++) {
#pragma unroll
        for (int nj = 0; nj < 4; nj++) {
            int r = row0 + rL + mi * 16;
            int cc = col0 + cL + nj * 8;
            float v0 = a_ * acc[mi][nj][0];
            float v1 = a_ * acc[mi][nj][1];
            float v2 = a_ * acc[mi][nj][2];
            float v3 = a_ * acc[mi][nj][3];
            if (useAdd) {
                uint32_t w0 = *(const uint32_t*)(Add + (size_t)r * NDIM + cc);
                uint32_t w1 = *(const uint32_t*)(Add + (size_t)(r + 8) * NDIM + cc);
                __nv_bfloat162 b0 = *reinterpret_cast<__nv_bfloat162*>(&w0);
                __nv_bfloat162 b1 = *reinterpret_cast<__nv_bfloat162*>(&w1);
                v0 += b_ * __bfloat162float(b0.x);
                v1 += b_ * __bfloat162float(b0.y);
                v2 += b_ * __bfloat162float(b1.x);
                v3 += b_ * __bfloat162float(b1.y);
            }
            __nv_bfloat162 p0 = __floats2bfloat162_rn(v0, v1);
            __nv_bfloat162 p1 = __floats2bfloat162_rn(v2, v3);
            *(uint32_t*)(gC + (size_t)m * MAT + (size_t)r * NDIM + cc)       = *reinterpret_cast<uint32_t*>(&p0);
            *(uint32_t*)(gC + (size_t)m * MAT + (size_t)(r + 8) * NDIM + cc) = *reinterpret_cast<uint32_t*>(&p1);
            if (mirror) {
                int lr = rL + mi * 16, lc = cL + nj * 8;
                stageB[lr * 130 + lc]           = ((uint16_t*)&p0)[0];
                stageB[lr * 130 + lc + 1]       = ((uint16_t*)&p0)[1];
                stageB[(lr + 8) * 130 + lc]     = ((uint16_t*)&p1)[0];
                stageB[(lr + 8) * 130 + lc + 1] = ((uint16_t*)&p1)[1];
            }
        }
    }

    if (mirror) {
        __syncthreads();
        int c = tid >> 1;
        int r0 = (tid & 1) * 64;
        bf16* Crow = gC + (size_t)m * MAT + (size_t)(col0 + c) * NDIM + row0 + r0;
#pragma unroll
        for (int q = 0; q < 8; q++) {
            union { uint16_t h[8]; uint4 v; } u;
#pragma unroll
            for (int e = 0; e < 8; e++)
                u.h[e] = stageB[(r0 + q * 8 + e) * 130 + c];
            *(uint4*)(Crow + q * 8) = u.v;
        }
    }
}

// ================= small kernels =================
__global__ void init_k(const float* __restrict__ ir, const float* __restrict__ vi,
                       bf16* __restrict__ X, bf16* __restrict__ Ab) {
    int m = blockIdx.y;
    const float* src = (m < CH) ? ir + (size_t)m * MAT : vi + (size_t)(m - CH) * MAT;
    int i = blockIdx.x * blockDim.x + threadIdx.x;     // float4 idx
    float4 v = ((const float4*)src)[i];
    v.x += EPS; v.y += EPS; v.z += EPS; v.w += EPS;
    __nv_bfloat162 a0 = __floats2bfloat162_rn(v.x, v.y);
    __nv_bfloat162 a1 = __floats2bfloat162_rn(v.z, v.w);
    __nv_bfloat162* Ap = (__nv_bfloat162*)(Ab + (size_t)m * MAT);
    __nv_bfloat162* Xp = (__nv_bfloat162*)(X + (size_t)m * MAT);
    Ap[2 * i] = a0; Ap[2 * i + 1] = a1;
    Xp[2 * i] = a0; Xp[2 * i + 1] = a1;
}

// gamma = (1.05 * ||S||_F)^{-1/2}; store quintic coefs scaled by gamma powers
__global__ void snorm_k(const bf16* __restrict__ S) {
    int m = blockIdx.x;
    const bf16* s = S + (size_t)m * MAT;
    float acc = 0.f;
    for (int i = threadIdx.x; i < MAT; i += blockDim.x) {
        float v = __bfloat162float(s[i]);
        acc += v * v;
    }
    acc = block_reduce(acc);
    if (threadIdx.x == 0) {
        float nf = sqrtf(acc);                // ||S||_F  >= sigma_max^2
        float g = rsqrtf(1.05f * nf);         // gamma
        float g2 = g * g;
        g_cX[m] = 3.4445f * g;
        g_cB[m] = -4.7750f * g2 * g;
        g_cA[m] = 2.0315f * g2 * g2 * g;
    }
}

// p = 1.5*<X, A+eps> - 0.5*sum(partials)
__global__ void pfin_k(const float* __restrict__ ir, const float* __restrict__ vi,
                       const bf16* __restrict__ X) {
    int m = blockIdx.x;
    const float* src = (m < CH) ? ir + (size_t)m * MAT : vi + (size_t)(m - CH) * MAT;
    const bf16* x = X + (size_t)m * MAT;
    float t1 = 0.f;
    for (int i = threadIdx.x; i < MAT; i += blockDim.x)
        t1 += __bfloat162float(x[i]) * (src[i] + EPS);
    t1 = block_reduce(t1);
    if (threadIdx.x == 0) {
        float t2 = 0.f;
#pragma unroll
        for (int k = 0; k < 9; k++) t2 += g_part[m * 9 + k];
        g_p[m] = 1.5f * t1 - 0.5f * t2;
    }
}

__global__ void final_kernel(const float* __restrict__ ir, const float* __restrict__ vi,
                             float* __restrict__ out) {
    int idx = blockIdx.x * blockDim.x + threadIdx.x;
    int c = idx / (MAT / 4);
    float p1 = g_p[c], p2 = g_p[c + CH];
    float d = p1 + p2 + EPS;
    float w1 = p1 / d, w2 = p2 / d;
    float4 a = ((const float4*)ir)[idx];
    float4 b = ((const float4*)vi)[idx];
    float4 o;
    o.x = w1 * a.x + w2 * b.x;
    o.y = w1 * a.y + w2 * b.y;
    o.z = w1 * a.z + w2 * b.z;
    o.w = w1 * a.w + w2 * b.w;
    ((float4*)out)[idx] = o;
}

extern "C" void kernel_launch(void* const* d_in, const int* in_sizes, int n_in,
                              void* d_out, int out_size) {
    const float* ir = (const float*)d_in[0];
    const float* vi = (const float*)d_in[1];
    float* out = (float*)d_out;

    bf16 *Xa, *Xb, *S, *Bq, *Ab;
    float *cA, *cB, *cX;
    cudaGetSymbolAddress((void**)&Xa, g_Xa);
    cudaGetSymbolAddress((void**)&Xb, g_Xb);
    cudaGetSymbolAddress((void**)&S,  g_S);
    cudaGetSymbolAddress((void**)&Bq, g_Bq);
    cudaGetSymbolAddress((void**)&Ab, g_Ab);
    cudaGetSymbolAddress((void**)&cA, g_cA);
    cudaGetSymbolAddress((void**)&cB, g_cB);
    cudaGetSymbolAddress((void**)&cX, g_cX);

    cudaFuncSetAttribute(gemm_mma<0,0,0>, cudaFuncAttributeMaxDynamicSharedMemorySize, GSMEM);
    cudaFuncSetAttribute(gemm_mma<0,1,0>, cudaFuncAttributeMaxDynamicSharedMemorySize, GSMEM);
    cudaFuncSetAttribute(gemm_mma<1,0,0>, cudaFuncAttributeMaxDynamicSharedMemorySize, GSMEM);
    cudaFuncSetAttribute(gemm_mma<0,0,1>, cudaFuncAttributeMaxDynamicSharedMemorySize, GSMEM);

    dim3 gFull(3, 3, NMAT);
    dim3 gSym(6, 1, NMAT);

    init_k<<<dim3(MAT / 4 / 256, NMAT), 256>>>(ir, vi, Xa, Ab);

    bf16* Xc = Xa;
    bf16* Xn = Xb;
    const float qa = 3.4445f, qb = -4.7750f, qc = 2.0315f;

    // --- quintic iteration 1 with spectral-bound scaling folded into coefs ---
    gemm_mma<0,1,0><<<gSym,  256, GSMEM>>>(Xc, Xc, Xc, S,  1.0f, 0.0f, nullptr, nullptr);
    snorm_k<<<NMAT, 512>>>(S);
    gemm_mma<0,1,0><<<gSym,  256, GSMEM>>>(S,  S,  S,  Bq, 0.f,  0.f,  cA, cB);   // Bq = qc g^5 S^2 + qb g^3 S
    gemm_mma<1,0,0><<<gFull, 256, GSMEM>>>(Bq, Xc, Xc, Xn, 1.0f, 0.f,  nullptr, cX); // X' = Bq X + qa g X
    { bf16* t = Xc; Xc = Xn; Xn = t; }

    // --- 3 plain quintic iterations ---
    for (int it = 0; it < 3; it++) {
        gemm_mma<0,1,0><<<gSym,  256, GSMEM>>>(Xc, Xc, Xc, S,  1.0f, 0.0f, nullptr, nullptr);
        gemm_mma<0,1,0><<<gSym,  256, GSMEM>>>(S,  S,  S,  Bq, qc,   qb,   nullptr, nullptr);
        gemm_mma<1,0,0><<<gFull, 256, GSMEM>>>(Bq, Xc, Xc, Xn, 1.0f, qa,   nullptr, nullptr);
        bf16* t = Xc; Xc = Xn; Xn = t;
    }
    // --- 1 cubic Newton-Schulz ---
    gemm_mma<0,1,0><<<gSym,  256, GSMEM>>>(Xc, Xc, Xc, S,  1.0f, 0.0f, nullptr, nullptr);
    gemm_mma<1,0,0><<<gFull, 256, GSMEM>>>(S,  Xc, Xc, Xn, -0.5f, 1.5f, nullptr, nullptr);
    { bf16* t = Xc; Xc = Xn; Xn = t; }

    // --- exact polish folded into trace: p = 1.5<X,A> - 0.5<XX^T, A X^T> ---
    gemm_mma<0,1,0><<<gSym,  256, GSMEM>>>(Xc, Xc, Xc, S,  1.0f, 0.0f, nullptr, nullptr);
    gemm_mma<0,0,1><<<gFull, 256, GSMEM>>>(Ab, Xc, S,  nullptr, 1.0f, 0.0f, nullptr, nullptr);

    pfin_k<<<NMAT, 512>>>(ir, vi, Xc);
    final_kernel<<<(CH * MAT / 4) / 256, 256>>>(ir, vi, out);
}

// round 10
// speedup vs baseline: 1.5071x; 1.5071x over previous
#include <cuda_runtime.h>
#include <cuda_bf16.h>
#include <cstdint>

#define NDIM 384
#define MAT  (NDIM*NDIM)
#define NMAT 256
#define CH   128
#define EPS  1e-5f

typedef __nv_bfloat16 bf16;

// ---- scratch (static device globals; no allocation) ----
__device__ bf16  g_Xa[(size_t)NMAT*MAT];
__device__ bf16  g_Xb[(size_t)NMAT*MAT];
__device__ bf16  g_S [(size_t)NMAT*MAT];
__device__ bf16  g_Bq[(size_t)NMAT*MAT];
__device__ bf16  g_Ab[(size_t)NMAT*MAT];
__device__ float g_cA[NMAT];        // qc * gamma^5
__device__ float g_cB[NMAT];        // qb * gamma^3
__device__ float g_cX[NMAT];        // qa * gamma
__device__ float g_part[NMAT * 9];  // per-tile <G,S> partials
__device__ float g_p [NMAT];

__device__ __forceinline__ uint32_t smem_to_u32(const void* p) {
    uint32_t a;
    asm("{ .reg .u64 t; cvta.to.shared.u64 t, %1; cvt.u32.u64 %0, t; }" : "=r"(a) : "l"(p));
    return a;
}

__device__ __forceinline__ float block_reduce(float s) {
    __shared__ float sh[32];
    for (int o = 16; o; o >>= 1) s += __shfl_down_sync(0xFFFFFFFFu, s, o);
    if ((threadIdx.x & 31) == 0) sh[threadIdx.x >> 5] = s;
    __syncthreads();
    float r = 0.f;
    if (threadIdx.x < 32) {
        r = (threadIdx.x < (blockDim.x >> 5)) ? sh[threadIdx.x] : 0.f;
        for (int o = 16; o; o >>= 1) r += __shfl_down_sync(0xFFFFFFFFu, r, o);
    }
    __syncthreads();
    return r;
}

// ================= batched bf16 GEMM via mma.sync =================
// TRANS_B=0 (NT): C = a*A*B^T + b*Add   TRANS_B=1 (NN): C = a*A*B + b*Add
// SYMM=1: output symmetric, 6 upper tiles + mirrored writes.
// DOT=1: no C written; accumulate <a*A*B^T, Add> per-CTA into g_part.
// 2-stage cp.async pipeline: 64KB smem/CTA so 2 CTAs co-reside per SM
// (smem was the occupancy limiter at 96KB; regs allow exactly 2x32K).
#define GSMEM (2 * 32768)

template<int TRANS_B, int SYMM, int DOT>
__global__ void __launch_bounds__(256) gemm_mma(
    const bf16* __restrict__ gA, const bf16* __restrict__ gB,
    const bf16* __restrict__ gAdd, bf16* __restrict__ gC,
    float alpha, float beta,
    const float* __restrict__ aArr, const float* __restrict__ bArr)
{
    extern __shared__ char smem_raw[];
    const int m = blockIdx.z;
    int bi, bj;
    if (SYMM) {
        int x = blockIdx.x;
        bi = (x < 3) ? 0 : (x < 5) ? 1 : 2;
        bj = (x < 3) ? x : (x < 5) ? (x - 2) : 2;
    } else {
        bi = blockIdx.y; bj = blockIdx.x;
    }
    const int row0 = bi * 128, col0 = bj * 128;
    const bf16* A = gA + (size_t)m * MAT + (size_t)row0 * NDIM;
    const bf16* B = TRANS_B ? (gB + (size_t)m * MAT + col0)
                            : (gB + (size_t)m * MAT + (size_t)col0 * NDIM);
    const uint32_t sBase = smem_to_u32(smem_raw);
    const int tid = threadIdx.x;
    const int wid = tid >> 5, lane = tid & 31;
    const int wm = wid >> 2, wn = wid & 3;

    auto issue = [&](int kt, int stage) {
        uint32_t aD = sBase + stage * 32768;
        uint32_t bD = aD + 16384;
        const bf16* aSrc = A + kt * 64;
#pragma unroll
        for (int i = 0; i < 4; i++) {
            int c = tid + i * 256;
            int row = c >> 3, u = c & 7;
            uint32_t sw = (uint32_t)(row * 128 + ((u ^ (row & 7)) << 4));
            asm volatile("cp.async.cg.shared.global [%0], [%1], 16;"
                :: "r"(aD + sw), "l"(aSrc + (size_t)row * NDIM + u * 8) : "memory");
        }
        if (TRANS_B) {
            const bf16* bSrc = B + (size_t)(kt * 64) * NDIM;
#pragma unroll
            for (int i = 0; i < 4; i++) {
                int c = tid + i * 256;
                int row = c >> 4, u = c & 15;
                uint32_t sw = (uint32_t)(row * 256 + ((u ^ (row & 7)) << 4));
                asm volatile("cp.async.cg.shared.global [%0], [%1], 16;"
                    :: "r"(bD + sw), "l"(bSrc + (size_t)row * NDIM + u * 8) : "memory");
            }
        } else {
            const bf16* bSrc = B + kt * 64;
#pragma unroll
            for (int i = 0; i < 4; i++) {
                int c = tid + i * 256;
                int row = c >> 3, u = c & 7;
                uint32_t sw = (uint32_t)(row * 128 + ((u ^ (row & 7)) << 4));
                asm volatile("cp.async.cg.shared.global [%0], [%1], 16;"
                    :: "r"(bD + sw), "l"(bSrc + (size_t)row * NDIM + u * 8) : "memory");
            }
        }
        asm volatile("cp.async.commit_group;" ::: "memory");
    };

    float acc[4][4][4];
#pragma unroll
    for (int a = 0; a < 4; a++)
#pragma unroll
        for (int b = 0; b < 4; b++)
#pragma unroll
            for (int c = 0; c < 4; c++) acc[a][b][c] = 0.f;

    issue(0, 0);
    issue(1, 1);

    for (int kt = 0; kt < 6; kt++) {
        int stage = kt & 1;
        if (kt < 5) asm volatile("cp.async.wait_group 1;" ::: "memory");
        else        asm volatile("cp.async.wait_group 0;" ::: "memory");
        __syncthreads();
        uint32_t aS = sBase + stage * 32768;
        uint32_t bS = aS + 16384;
#pragma unroll
        for (int ks = 0; ks < 4; ks++) {
            uint32_t af[4][4];
            uint32_t bfr[4][2];
#pragma unroll
            for (int mi = 0; mi < 4; mi++) {
                int row = wm * 64 + mi * 16 + (lane & 15);
                int u = ks * 2 + (lane >> 4);
                uint32_t addr = aS + row * 128 + ((u ^ (row & 7)) << 4);
                asm volatile("ldmatrix.sync.aligned.m8n8.x4.shared.b16 {%0,%1,%2,%3}, [%4];"
                    : "=r"(af[mi][0]), "=r"(af[mi][1]), "=r"(af[mi][2]), "=r"(af[mi][3])
                    : "r"(addr));
            }
            if (TRANS_B) {
#pragma unroll
                for (int bj2 = 0; bj2 < 2; bj2++) {
                    int krow = ks * 16 + (lane & 15);
                    int ugrp = ((wn * 32 + bj2 * 16) >> 3) + (lane >> 4);
                    uint32_t addr = bS + krow * 256 + ((ugrp ^ (krow & 7)) << 4);
                    asm volatile("ldmatrix.sync.aligned.m8n8.x4.trans.shared.b16 {%0,%1,%2,%3}, [%4];"
                        : "=r"(bfr[bj2*2][0]), "=r"(bfr[bj2*2][1]),
                          "=r"(bfr[bj2*2+1][0]), "=r"(bfr[bj2*2+1][1])
                        : "r"(addr));
                }
            } else {
#pragma unroll
                for (int bj2 = 0; bj2 < 2; bj2++) {
                    int nLocal = wn * 32 + bj2 * 16 + ((lane >> 4) << 3) + (lane & 7);
                    int u = ks * 2 + ((lane >> 3) & 1);
                    uint32_t addr = bS + nLocal * 128 + ((u ^ (nLocal & 7)) << 4);
                    asm volatile("ldmatrix.sync.aligned.m8n8.x4.shared.b16 {%0,%1,%2,%3}, [%4];"
                        : "=r"(bfr[bj2*2][0]), "=r"(bfr[bj2*2][1]),
                          "=r"(bfr[bj2*2+1][0]), "=r"(bfr[bj2*2+1][1])
                        : "r"(addr));
                }
            }
#pragma unroll
            for (int mi = 0; mi < 4; mi++)
#pragma unroll
                for (int nj = 0; nj < 4; nj++) {
                    asm volatile(
                        "mma.sync.aligned.m16n8k16.row.col.f32.bf16.bf16.f32 "
                        "{%0,%1,%2,%3}, {%4,%5,%6,%7}, {%8,%9}, {%0,%1,%2,%3};"
                        : "+f"(acc[mi][nj][0]), "+f"(acc[mi][nj][1]),
                          "+f"(acc[mi][nj][2]), "+f"(acc[mi][nj][3])
                        : "r"(af[mi][0]), "r"(af[mi][1]), "r"(af[mi][2]), "r"(af[mi][3]),
                          "r"(bfr[nj][0]), "r"(bfr[nj][1]));
                }
        }
        if (kt + 2 < 6) {
            __syncthreads();           // all warps done reading this stage
            issue(kt + 2, stage);      // refill the stage just consumed
        }
    }

    // ---- epilogue ----
    float a_ = aArr ? aArr[m] : alpha;
    float b_ = bArr ? bArr[m] : beta;
    bool useAdd = (bArr != nullptr) || (beta != 0.f);

    const int rL = wm * 64 + (lane >> 2);
    const int cL = wn * 32 + (lane & 3) * 2;
    const bf16* Add = gAdd + (size_t)m * MAT;

    if (DOT) {
        float part = 0.f;
#pragma unroll
        for (int mi = 0; mi < 4; mi++)
#pragma unroll
            for (int nj = 0; nj < 4; nj++) {
                int r = row0 + rL + mi * 16;
                int cc = col0 + cL + nj * 8;
                uint32_t w0 = *(const uint32_t*)(Add + (size_t)r * NDIM + cc);
                uint32_t w1 = *(const uint32_t*)(Add + (size_t)(r + 8) * NDIM + cc);
                __nv_bfloat162 b0 = *reinterpret_cast<__nv_bfloat162*>(&w0);
                __nv_bfloat162 b1 = *reinterpret_cast<__nv_bfloat162*>(&w1);
                part += acc[mi][nj][0] * __bfloat162float(b0.x);
                part += acc[mi][nj][1] * __bfloat162float(b0.y);
                part += acc[mi][nj][2] * __bfloat162float(b1.x);
                part += acc[mi][nj][3] * __bfloat162float(b1.y);
            }
        part = block_reduce(part);
        if (tid == 0) g_part[m * 9 + bi * 3 + bj] = part;
        return;
    }

    const bool mirror = SYMM && (row0 != col0);
    if (mirror) __syncthreads();
    uint16_t* stageB = (uint16_t*)smem_raw;   // stride 130

#pragma unroll
    for (int mi = 0; mi < 4; mi++) {
#pragma unroll
        for (int nj = 0; nj < 4; nj++) {
            int r = row0 + rL + mi * 16;
            int cc = col0 + cL + nj * 8;
            float v0 = a_ * acc[mi][nj][0];
            float v1 = a_ * acc[mi][nj][1];
            float v2 = a_ * acc[mi][nj][2];
            float v3 = a_ * acc[mi][nj][3];
            if (useAdd) {
                uint32_t w0 = *(const uint32_t*)(Add + (size_t)r * NDIM + cc);
                uint32_t w1 = *(const uint32_t*)(Add + (size_t)(r + 8) * NDIM + cc);
                __nv_bfloat162 b0 = *reinterpret_cast<__nv_bfloat162*>(&w0);
                __nv_bfloat162 b1 = *reinterpret_cast<__nv_bfloat162*>(&w1);
                v0 += b_ * __bfloat162float(b0.x);
                v1 += b_ * __bfloat162float(b0.y);
                v2 += b_ * __bfloat162float(b1.x);
                v3 += b_ * __bfloat162float(b1.y);
            }
            __nv_bfloat162 p0 = __floats2bfloat162_rn(v0, v1);
            __nv_bfloat162 p1 = __floats2bfloat162_rn(v2, v3);
            *(uint32_t*)(gC + (size_t)m * MAT + (size_t)r * NDIM + cc)       = *reinterpret_cast<uint32_t*>(&p0);
            *(uint32_t*)(gC + (size_t)m * MAT + (size_t)(r + 8) * NDIM + cc) = *reinterpret_cast<uint32_t*>(&p1);
            if (mirror) {
                int lr = rL + mi * 16, lc = cL + nj * 8;
                stageB[lr * 130 + lc]           = ((uint16_t*)&p0)[0];
                stageB[lr * 130 + lc + 1]       = ((uint16_t*)&p0)[1];
                stageB[(lr + 8) * 130 + lc]     = ((uint16_t*)&p1)[0];
                stageB[(lr + 8) * 130 + lc + 1] = ((uint16_t*)&p1)[1];
            }
        }
    }

    if (mirror) {
        __syncthreads();
        int c = tid >> 1;
        int r0 = (tid & 1) * 64;
        bf16* Crow = gC + (size_t)m * MAT + (size_t)(col0 + c) * NDIM + row0 + r0;
#pragma unroll
        for (int q = 0; q < 8; q++) {
            union { uint16_t h[8]; uint4 v; } u;
#pragma unroll
            for (int e = 0; e < 8; e++)
                u.h[e] = stageB[(r0 + q * 8 + e) * 130 + c];
            *(uint4*)(Crow + q * 8) = u.v;
        }
    }
}

// ================= small kernels =================
__global__ void init_k(const float* __restrict__ ir, const float* __restrict__ vi,
                       bf16* __restrict__ X, bf16* __restrict__ Ab) {
    int m = blockIdx.y;
    const float* src = (m < CH) ? ir + (size_t)m * MAT : vi + (size_t)(m - CH) * MAT;
    int i = blockIdx.x * blockDim.x + threadIdx.x;     // float4 idx
    float4 v = ((const float4*)src)[i];
    v.x += EPS; v.y += EPS; v.z += EPS; v.w += EPS;
    __nv_bfloat162 a0 = __floats2bfloat162_rn(v.x, v.y);
    __nv_bfloat162 a1 = __floats2bfloat162_rn(v.z, v.w);
    __nv_bfloat162* Ap = (__nv_bfloat162*)(Ab + (size_t)m * MAT);
    __nv_bfloat162* Xp = (__nv_bfloat162*)(X + (size_t)m * MAT);
    Ap[2 * i] = a0; Ap[2 * i + 1] = a1;
    Xp[2 * i] = a0; Xp[2 * i + 1] = a1;
}

// gamma = (1.05 * ||S||_F)^{-1/2}; store quintic coefs scaled by gamma powers
__global__ void snorm_k(const bf16* __restrict__ S) {
    int m = blockIdx.x;
    const bf16* s = S + (size_t)m * MAT;
    float acc = 0.f;
    for (int i = threadIdx.x; i < MAT; i += blockDim.x) {
        float v = __bfloat162float(s[i]);
        acc += v * v;
    }
    acc = block_reduce(acc);
    if (threadIdx.x == 0) {
        float nf = sqrtf(acc);                // ||S||_F  >= sigma_max^2
        float g = rsqrtf(1.05f * nf);         // gamma
        float g2 = g * g;
        g_cX[m] = 3.4445f * g;
        g_cB[m] = -4.7750f * g2 * g;
        g_cA[m] = 2.0315f * g2 * g2 * g;
    }
}

// p = 1.5*<X, A+eps> - 0.5*sum(partials)
__global__ void pfin_k(const float* __restrict__ ir, const float* __restrict__ vi,
                       const bf16* __restrict__ X) {
    int m = blockIdx.x;
    const float* src = (m < CH) ? ir + (size_t)m * MAT : vi + (size_t)(m - CH) * MAT;
    const bf16* x = X + (size_t)m * MAT;
    float t1 = 0.f;
    for (int i = threadIdx.x; i < MAT; i += blockDim.x)
        t1 += __bfloat162float(x[i]) * (src[i] + EPS);
    t1 = block_reduce(t1);
    if (threadIdx.x == 0) {
        float t2 = 0.f;
#pragma unroll
        for (int k = 0; k < 9; k++) t2 += g_part[m * 9 + k];
        g_p[m] = 1.5f * t1 - 0.5f * t2;
    }
}

__global__ void final_kernel(const float* __restrict__ ir, const float* __restrict__ vi,
                             float* __restrict__ out) {
    int idx = blockIdx.x * blockDim.x + threadIdx.x;
    int c = idx / (MAT / 4);
    float p1 = g_p[c], p2 = g_p[c + CH];
    float d = p1 + p2 + EPS;
    float w1 = p1 / d, w2 = p2 / d;
    float4 a = ((const float4*)ir)[idx];
    float4 b = ((const float4*)vi)[idx];
    float4 o;
    o.x = w1 * a.x + w2 * b.x;
    o.y = w1 * a.y + w2 * b.y;
    o.z = w1 * a.z + w2 * b.z;
    o.w = w1 * a.w + w2 * b.w;
    ((float4*)out)[idx] = o;
}

extern "C" void kernel_launch(void* const* d_in, const int* in_sizes, int n_in,
                              void* d_out, int out_size) {
    const float* ir = (const float*)d_in[0];
    const float* vi = (const float*)d_in[1];
    float* out = (float*)d_out;

    bf16 *Xa, *Xb, *S, *Bq, *Ab;
    float *cA, *cB, *cX;
    cudaGetSymbolAddress((void**)&Xa, g_Xa);
    cudaGetSymbolAddress((void**)&Xb, g_Xb);
    cudaGetSymbolAddress((void**)&S,  g_S);
    cudaGetSymbolAddress((void**)&Bq, g_Bq);
    cudaGetSymbolAddress((void**)&Ab, g_Ab);
    cudaGetSymbolAddress((void**)&cA, g_cA);
    cudaGetSymbolAddress((void**)&cB, g_cB);
    cudaGetSymbolAddress((void**)&cX, g_cX);

    cudaFuncSetAttribute(gemm_mma<0,0,0>, cudaFuncAttributeMaxDynamicSharedMemorySize, GSMEM);
    cudaFuncSetAttribute(gemm_mma<0,1,0>, cudaFuncAttributeMaxDynamicSharedMemorySize, GSMEM);
    cudaFuncSetAttribute(gemm_mma<1,0,0>, cudaFuncAttributeMaxDynamicSharedMemorySize, GSMEM);
    cudaFuncSetAttribute(gemm_mma<0,0,1>, cudaFuncAttributeMaxDynamicSharedMemorySize, GSMEM);

    dim3 gFull(3, 3, NMAT);
    dim3 gSym(6, 1, NMAT);

    init_k<<<dim3(MAT / 4 / 256, NMAT), 256>>>(ir, vi, Xa, Ab);

    bf16* Xc = Xa;
    bf16* Xn = Xb;
    const float qa = 3.4445f, qb = -4.7750f, qc = 2.0315f;

    // --- quintic iteration 1 with spectral-bound scaling folded into coefs ---
    gemm_mma<0,1,0><<<gSym,  256, GSMEM>>>(Xc, Xc, Xc, S,  1.0f, 0.0f, nullptr, nullptr);
    snorm_k<<<NMAT, 512>>>(S);
    gemm_mma<0,1,0><<<gSym,  256, GSMEM>>>(S,  S,  S,  Bq, 0.f,  0.f,  cA, cB);   // Bq = qc g^5 S^2 + qb g^3 S
    gemm_mma<1,0,0><<<gFull, 256, GSMEM>>>(Bq, Xc, Xc, Xn, 1.0f, 0.f,  nullptr, cX); // X' = Bq X + qa g X
    { bf16* t = Xc; Xc = Xn; Xn = t; }

    // --- 3 plain quintic iterations ---
    for (int it = 0; it < 3; it++) {
        gemm_mma<0,1,0><<<gSym,  256, GSMEM>>>(Xc, Xc, Xc, S,  1.0f, 0.0f, nullptr, nullptr);
        gemm_mma<0,1,0><<<gSym,  256, GSMEM>>>(S,  S,  S,  Bq, qc,   qb,   nullptr, nullptr);
        gemm_mma<1,0,0><<<gFull, 256, GSMEM>>>(Bq, Xc, Xc, Xn, 1.0f, qa,   nullptr, nullptr);
        bf16* t = Xc; Xc = Xn; Xn = t;
    }
    // --- 1 cubic Newton-Schulz ---
    gemm_mma<0,1,0><<<gSym,  256, GSMEM>>>(Xc, Xc, Xc, S,  1.0f, 0.0f, nullptr, nullptr);
    gemm_mma<1,0,0><<<gFull, 256, GSMEM>>>(S,  Xc, Xc, Xn, -0.5f, 1.5f, nullptr, nullptr);
    { bf16* t = Xc; Xc = Xn; Xn = t; }

    // --- exact polish folded into trace: p = 1.5<X,A> - 0.5<XX^T, A X^T> ---
    gemm_mma<0,1,0><<<gSym,  256, GSMEM>>>(Xc, Xc, Xc, S,  1.0f, 0.0f, nullptr, nullptr);
    gemm_mma<0,0,1><<<gFull, 256, GSMEM>>>(Ab, Xc, S,  nullptr, 1.0f, 0.0f, nullptr, nullptr);

    pfin_k<<<NMAT, 512>>>(ir, vi, Xc);
    final_kernel<<<(CH * MAT / 4) / 256, 256>>>(ir, vi, out);
}